// round 5
// baseline (speedup 1.0000x reference)
#include <cuda_runtime.h>
#include <math.h>

#define BSZ   256
#define ISIZE 256
#define HSIZE 512
#define BH    (BSZ*HSIZE)

#define BK 16
#define NSLOTS 768            // 256 gate units + 512 reduce units, interleaved
#define GRID1 296             // 2 CTAs per SM x 148 SMs

// Scratch (device globals)
__device__ __align__(16) float g_prex[4*BH];   // x-side gate partials
__device__ __align__(16) float g_preh[4*BH];   // h-side gate partials
__device__ __align__(16) float g_hredp[2*BH];  // hred partials (2 h-halves)
__device__ __align__(16) float g_ei[BH];       // eta*its per (b,k)

// ---------------------------------------------------------------------------
// K1: persistent heterogeneous kernel, 296 CTAs x 512 threads.
// Slot s (0..767): s%3==1 -> gate unit s/3 (256 units);
//                  s%3==0 -> reduce unit s/3; s%3==2 -> reduce unit 256+s/3.
// Each CTA (stride 296) hits all residues mod 3 -> exactly one gate unit per
// CTA, staggered in time -> gates hide in the reduce's bandwidth shadow.
// ---------------------------------------------------------------------------
__global__ __launch_bounds__(512, 2)
void k1(const float* __restrict__ x, const float* __restrict__ h0,
        const float* __restrict__ hebb,
        const float* __restrict__ x2f, const float* __restrict__ x2i,
        const float* __restrict__ x2o, const float* __restrict__ x2c,
        const float* __restrict__ h2f, const float* __restrict__ h2i,
        const float* __restrict__ h2o, const float* __restrict__ w)
{
    __shared__ union {
        struct { float sh0[256]; float4 sp[512]; } r;      // reduce: 9KB
        struct { float As[BK][68]; float Ws[BK][68]; } t;  // gates: 8.7KB
    } sm;

    int tid = threadIdx.x;

    for (int s = blockIdx.x; s < NSLOTS; s += GRID1) {
        int res = s % 3;
        if (res != 1) {
            // ---------------- reduce unit: (b, half) over 256 rows ----------
            int ru = (res == 0) ? (s / 3) : (256 + s / 3);
            int b = ru >> 1;
            int half = ru & 1;
            if (tid < 256) sm.r.sh0[tid] = h0[b * HSIZE + half * 256 + tid];
            __syncthreads();
            int g = tid >> 7, t = tid & 127;     // 4 groups x 64 rows, 128 f4 cols
            const float4* hb4 = (const float4*)(hebb + (size_t)b * HSIZE * HSIZE)
                                + (size_t)(half * 256 + g * 64) * 128 + t;
            const float* s0 = &sm.r.sh0[g * 64];
            float4 acc = make_float4(0.f, 0.f, 0.f, 0.f);
#pragma unroll 8
            for (int h = 0; h < 64; ++h) {
                float sv = s0[h];
                float4 v = hb4[(size_t)h * 128];
                acc.x = fmaf(sv, v.x, acc.x);
                acc.y = fmaf(sv, v.y, acc.y);
                acc.z = fmaf(sv, v.z, acc.z);
                acc.w = fmaf(sv, v.w, acc.w);
            }
            sm.r.sp[tid] = acc;
            __syncthreads();
            if (tid < 128) {
                float4 a = sm.r.sp[tid];
                float4 b2 = sm.r.sp[128 + tid];
                float4 c = sm.r.sp[256 + tid];
                float4 d = sm.r.sp[384 + tid];
                a.x += b2.x + c.x + d.x;
                a.y += b2.y + c.y + d.y;
                a.z += b2.z + c.z + d.z;
                a.w += b2.w + c.w + d.w;
                ((float4*)(g_hredp + half * BH + b * HSIZE))[tid] = a;
            }
            __syncthreads();
        } else {
            // ---------------- gate GEMM unit ------------------------------
            int u = s / 3;                 // 0..255
            int phase = u >> 7;            // 0 = x-side, 1 = h-side
            int r = u & 127;
            int gate = r >> 5;
            int ct = r & 31;
            int bn0 = (ct & 7) * 64;       // k offset
            int bm0 = (ct >> 3) * 64;      // b offset
            const float* A = phase ? h0 : x;
            int K = phase ? HSIZE : ISIZE;
            const float* W;
            if (phase == 0)
                W = (gate == 0) ? x2f : (gate == 1) ? x2i : (gate == 2) ? x2o : x2c;
            else
                W = (gate == 0) ? h2f : (gate == 1) ? h2i : (gate == 2) ? h2o : w;
            bool trans = (phase == 1) && (gate == 3);   // w is [h,k]

            int tx = tid & 15, ty = tid >> 4;           // ty: 0..31
            float acc[2][4] = {};

            for (int k0 = 0; k0 < K; k0 += BK) {
#pragma unroll
                for (int l = 0; l < 2; l++) {
                    int e = tid + l * 512; int rr = e >> 4; int cc = e & 15;
                    sm.t.As[cc][rr] = A[(size_t)(bm0 + rr) * K + k0 + cc];
                }
                if (trans) {
#pragma unroll
                    for (int l = 0; l < 2; l++) {
                        int e = tid + l * 512; int rr = e & 63; int cc = e >> 6;
                        sm.t.Ws[cc][rr] = W[(size_t)(k0 + cc) * HSIZE + bn0 + rr];
                    }
                } else {
#pragma unroll
                    for (int l = 0; l < 2; l++) {
                        int e = tid + l * 512; int rr = e >> 4; int cc = e & 15;
                        sm.t.Ws[cc][rr] = W[(size_t)(bn0 + rr) * K + k0 + cc];
                    }
                }
                __syncthreads();
#pragma unroll
                for (int kb = 0; kb < BK; kb++) {
                    float2 ra = *(const float2*)&sm.t.As[kb][ty * 2];
                    float4 rb = *(const float4*)&sm.t.Ws[kb][tx * 4];
                    float a[2] = {ra.x, ra.y};
                    float bv[4] = {rb.x, rb.y, rb.z, rb.w};
#pragma unroll
                    for (int i = 0; i < 2; i++)
#pragma unroll
                        for (int j = 0; j < 4; j++)
                            acc[i][j] = fmaf(a[i], bv[j], acc[i][j]);
                }
                __syncthreads();
            }
            float* outb = (phase ? g_preh : g_prex) + (size_t)gate * BH;
#pragma unroll
            for (int i = 0; i < 2; i++) {
                int bb = bm0 + ty * 2 + i;
#pragma unroll
                for (int j = 0; j < 4; j++)
                    outb[(size_t)bb * HSIZE + bn0 + tx * 4 + j] = acc[i][j];
            }
        }
    }
}

// ---------------------------------------------------------------------------
// K2: per-batch cell/hactiv + modulation scalar + ei = (m*mfw+mfb)*its.
// ---------------------------------------------------------------------------
__global__ __launch_bounds__(HSIZE)
void k2(const float* __restrict__ c0, const float* __restrict__ alpha,
        const float* __restrict__ x2f_b, const float* __restrict__ h2f_b,
        const float* __restrict__ x2i_b, const float* __restrict__ h2i_b,
        const float* __restrict__ x2o_b, const float* __restrict__ h2o_b,
        const float* __restrict__ x2c_b,
        const float* __restrict__ h2mod_w, const float* __restrict__ h2mod_b,
        const float* __restrict__ mfw, const float* __restrict__ mfb,
        float* __restrict__ out_hact, float* __restrict__ out_cell)
{
    __shared__ float sred[16];
    __shared__ float smv;
    int b = blockIdx.x;
    int k = threadIdx.x;
    int idx = b * HSIZE + k;

    float pf = g_prex[idx]          + g_preh[idx]          + x2f_b[k] + h2f_b[k];
    float pi = g_prex[BH + idx]     + g_preh[BH + idx]     + x2i_b[k] + h2i_b[k];
    float po = g_prex[2 * BH + idx] + g_preh[2 * BH + idx] + x2o_b[k] + h2o_b[k];
    float hred = g_hredp[idx] + g_hredp[BH + idx];
    float pc = g_prex[3 * BH + idx] + g_preh[3 * BH + idx] + x2c_b[k]
             + alpha[k] * hred;
    float fgt = 1.f / (1.f + expf(-pf));
    float ipt = 1.f / (1.f + expf(-pi));
    float opt = 1.f / (1.f + expf(-po));
    float its = tanhf(pc);
    float cell = fgt * c0[idx] + ipt * its;
    float hact = opt * tanhf(cell);
    out_cell[idx] = cell;
    out_hact[idx] = hact;

    float mv = hact * h2mod_w[k];
#pragma unroll
    for (int o = 16; o > 0; o >>= 1) mv += __shfl_down_sync(0xffffffffu, mv, o);
    if ((k & 31) == 0) sred[k >> 5] = mv;
    __syncthreads();
    if (k == 0) {
        float s = 0.f;
#pragma unroll
        for (int i = 0; i < 16; i++) s += sred[i];
        smv = tanhf(s + h2mod_b[0]);
    }
    __syncthreads();
    g_ei[idx] = fmaf(smv, mfw[k], mfb[k]) * its;
}

// ---------------------------------------------------------------------------
// K3: hebb_new[b,h,k] = clip(hebb + h0[b,h]*ei[b,k], -2, 2). Pure streaming.
// ---------------------------------------------------------------------------
__global__ __launch_bounds__(256)
void k3(const float4* __restrict__ hebb4, const float* __restrict__ h0,
        float4* __restrict__ out4)
{
    const float4* ei4 = reinterpret_cast<const float4*>(g_ei);
    int base = blockIdx.x * 1024 + threadIdx.x;
#pragma unroll
    for (int j = 0; j < 4; j++) {
        int idx = base + j * 256;
        int k4 = idx & 127;
        int bh = idx >> 7;
        int b = bh >> 9;
        float s = h0[bh];
        float4 e = ei4[(b << 7) + k4];
        float4 hv = hebb4[idx];
        float v;
        v = fmaf(s, e.x, hv.x); hv.x = fminf(fmaxf(v, -2.f), 2.f);
        v = fmaf(s, e.y, hv.y); hv.y = fminf(fmaxf(v, -2.f), 2.f);
        v = fmaf(s, e.z, hv.z); hv.z = fminf(fmaxf(v, -2.f), 2.f);
        v = fmaf(s, e.w, hv.w); hv.w = fminf(fmaxf(v, -2.f), 2.f);
        out4[idx] = hv;
    }
}

// ---------------------------------------------------------------------------
extern "C" void kernel_launch(void* const* d_in, const int* in_sizes, int n_in,
                              void* d_out, int out_size)
{
    const float* inputs  = (const float*)d_in[0];
    const float* h0      = (const float*)d_in[1];
    const float* c0      = (const float*)d_in[2];
    const float* hebb    = (const float*)d_in[3];
    const float* w       = (const float*)d_in[4];
    const float* alpha   = (const float*)d_in[5];
    const float* h2f_w   = (const float*)d_in[6];
    const float* h2f_b   = (const float*)d_in[7];
    const float* h2i_w   = (const float*)d_in[8];
    const float* h2i_b   = (const float*)d_in[9];
    const float* h2o_w   = (const float*)d_in[10];
    const float* h2o_b   = (const float*)d_in[11];
    const float* x2f_w   = (const float*)d_in[12];
    const float* x2f_b   = (const float*)d_in[13];
    const float* x2i_w   = (const float*)d_in[14];
    const float* x2i_b   = (const float*)d_in[15];
    const float* x2o_w   = (const float*)d_in[16];
    const float* x2o_b   = (const float*)d_in[17];
    const float* x2c_w   = (const float*)d_in[18];
    const float* x2c_b   = (const float*)d_in[19];
    const float* h2mod_w = (const float*)d_in[20];
    const float* h2mod_b = (const float*)d_in[21];
    const float* mfw     = (const float*)d_in[22];
    const float* mfb     = (const float*)d_in[23];

    float* out       = (float*)d_out;
    float* out_hact  = out;              // [B,H]
    float* out_cell  = out + BH;         // [B,H]
    float* out_hebb  = out + 2 * BH;     // [B,H,H]

    // K1: persistent heterogeneous grid (interleaved gates + reduce)
    k1<<<GRID1, 512>>>(inputs, h0, hebb,
                       x2f_w, x2i_w, x2o_w, x2c_w,
                       h2f_w, h2i_w, h2o_w, w);

    // K2: cell / hactiv / m / ei
    k2<<<BSZ, HSIZE>>>(c0, alpha, x2f_b, h2f_b, x2i_b, h2i_b, x2o_b, h2o_b,
                       x2c_b, h2mod_w, h2mod_b, mfw, mfb, out_hact, out_cell);

    // K3: hebb update (268MB R + 268MB W streaming)
    int nblk = (BSZ * HSIZE * HSIZE / 4) / 1024;   // 8192
    k3<<<nblk, 256>>>((const float4*)hebb, h0, (float4*)out_hebb);
}